// round 3
// baseline (speedup 1.0000x reference)
#include <cuda_runtime.h>
#include <math.h>
#include <stdint.h>

// ----------------------------------------------------------------------------
// GConvGRU with K=1 Cheb conv and H0 = 0 collapses to:
//   Z   = sigmoid(x @ W_xz + b_xz + b_hz)
//   Ht  = tanh   (x @ W_xh + b_xh + b_hh)
//   h   = elu((1-Z) * Ht)
//   out = h @ W_lin + b_lin
// Three 100000x256x256 GEMMs. Implemented with tf32 mma.sync (m16n8k8),
// fp32 accumulate, rounded inputs (cvt.rna.tf32).
// ----------------------------------------------------------------------------

#define M_NODES 100000
#define CH      256
#define MT      128   // CTA M tile
#define NT      128   // CTA N tile
#define KT      32    // K chunk
#define NCHUNK  (CH / KT)

#define APITCH  36            // words per A row (conflict-free frag loads)
#define BPITCH  136           // words per B row (8k+grp distinct banks)
#define ASZ     (MT * APITCH) // 4608 words per buffer
#define BSZ     (KT * BPITCH) // 4352 words per buffer

// scratch for h = elu(gru(x))  (static device global: allocation-free)
__device__ float g_h[(size_t)M_NODES * CH];

extern __shared__ uint32_t smem_u[];

__device__ __forceinline__ uint32_t f2tf(float x) {
    uint32_t r;
    asm("cvt.rna.tf32.f32 %0, %1;" : "=r"(r) : "f"(x));
    return r;
}

__device__ __forceinline__ void mma8(float c[4], const uint32_t a[4],
                                     uint32_t b0, uint32_t b1) {
    asm volatile(
        "mma.sync.aligned.m16n8k8.row.col.f32.tf32.tf32.f32 "
        "{%0,%1,%2,%3}, {%4,%5,%6,%7}, {%8,%9}, {%0,%1,%2,%3};\n"
        : "+f"(c[0]), "+f"(c[1]), "+f"(c[2]), "+f"(c[3])
        : "r"(a[0]), "r"(a[1]), "r"(a[2]), "r"(a[3]), "r"(b0), "r"(b1));
}

// ---------------------------------------------------------------------------
// Kernel 1: dual-GEMM gates + GRU/elu epilogue -> g_h
// ---------------------------------------------------------------------------
__global__ void __launch_bounds__(256, 1) gates_kernel(
    const float* __restrict__ x,
    const float* __restrict__ Wz, const float* __restrict__ bxz,
    const float* __restrict__ bhz,
    const float* __restrict__ Wh, const float* __restrict__ bxh,
    const float* __restrict__ bhh)
{
    const int tid  = threadIdx.x;
    const int warp = tid >> 5, lane = tid & 31;
    const int grp  = lane >> 2, t4 = lane & 3;
    const int wm   = warp & 3, wn = warp >> 2;
    const int wr   = wm * 32, wc = wn * 64;
    const int mbase = blockIdx.y * MT;
    const int nbase = blockIdx.x * NT;

    uint32_t* As = smem_u;                 // [2][ASZ]
    uint32_t* Bz = smem_u + 2 * ASZ;       // [2][BSZ]
    uint32_t* Bh = Bz + 2 * BSZ;           // [2][BSZ]

    float az[2][8][4], ah[2][8][4];
#pragma unroll
    for (int i = 0; i < 2; i++)
#pragma unroll
        for (int j = 0; j < 8; j++)
#pragma unroll
            for (int k = 0; k < 4; k++) { az[i][j][k] = 0.f; ah[i][j][k] = 0.f; }

    float4 va[4], vz[4], vh[4];

    auto ldA = [&](int kc) {
#pragma unroll
        for (int i = 0; i < 4; i++) {
            int f = tid + i * 256; int r = f >> 3, c4 = f & 7;
            int gr = mbase + r;
            va[i] = (gr < M_NODES)
                ? *reinterpret_cast<const float4*>(x + (size_t)gr * CH + kc + c4 * 4)
                : make_float4(0.f, 0.f, 0.f, 0.f);
        }
    };
    auto ldB = [&](const float* W, int kc, float4* v) {
#pragma unroll
        for (int i = 0; i < 4; i++) {
            int f = tid + i * 256; int k = f >> 5, n4 = f & 31;
            v[i] = *reinterpret_cast<const float4*>(W + (size_t)(kc + k) * CH + nbase + n4 * 4);
        }
    };
    auto stA = [&](int buf) {
        uint32_t* d = As + buf * ASZ;
#pragma unroll
        for (int i = 0; i < 4; i++) {
            int f = tid + i * 256; int r = f >> 3, c4 = f & 7;
            uint4 u = make_uint4(f2tf(va[i].x), f2tf(va[i].y), f2tf(va[i].z), f2tf(va[i].w));
            *reinterpret_cast<uint4*>(d + r * APITCH + c4 * 4) = u;
        }
    };
    auto stB = [&](uint32_t* base, int buf, float4* v) {
        uint32_t* d = base + buf * BSZ;
#pragma unroll
        for (int i = 0; i < 4; i++) {
            int f = tid + i * 256; int k = f >> 5, n4 = f & 31;
            uint4 u = make_uint4(f2tf(v[i].x), f2tf(v[i].y), f2tf(v[i].z), f2tf(v[i].w));
            *reinterpret_cast<uint4*>(d + k * BPITCH + n4 * 4) = u;
        }
    };

    auto compute = [&](int buf) {
        const uint32_t* A  = As + buf * ASZ;
        const uint32_t* BZ = Bz + buf * BSZ;
        const uint32_t* BH = Bh + buf * BSZ;
#pragma unroll
        for (int ks = 0; ks < 4; ks++) {
            int k0 = ks * 8;
            uint32_t a[2][4];
#pragma unroll
            for (int mi = 0; mi < 2; mi++) {
                int r = wr + mi * 16 + grp;
                a[mi][0] = A[r * APITCH + k0 + t4];
                a[mi][1] = A[(r + 8) * APITCH + k0 + t4];
                a[mi][2] = A[r * APITCH + k0 + 4 + t4];
                a[mi][3] = A[(r + 8) * APITCH + k0 + 4 + t4];
            }
#pragma unroll
            for (int ni = 0; ni < 8; ni++) {
                int c = wc + ni * 8 + grp;
                uint32_t b0 = BZ[(k0 + t4) * BPITCH + c];
                uint32_t b1 = BZ[(k0 + 4 + t4) * BPITCH + c];
                mma8(az[0][ni], a[0], b0, b1);
                mma8(az[1][ni], a[1], b0, b1);
                uint32_t d0 = BH[(k0 + t4) * BPITCH + c];
                uint32_t d1 = BH[(k0 + 4 + t4) * BPITCH + c];
                mma8(ah[0][ni], a[0], d0, d1);
                mma8(ah[1][ni], a[1], d0, d1);
            }
        }
    };

    // pipeline
    ldA(0); ldB(Wz, 0, vz); ldB(Wh, 0, vh);
    stA(0); stB(Bz, 0, vz); stB(Bh, 0, vh);
    __syncthreads();
#pragma unroll 1
    for (int ch = 0; ch < NCHUNK; ch++) {
        int cur = ch & 1;
        if (ch + 1 < NCHUNK) {
            int kc = (ch + 1) * KT;
            ldA(kc); ldB(Wz, kc, vz); ldB(Wh, kc, vh);
        }
        compute(cur);
        if (ch + 1 < NCHUNK) {
            stA(cur ^ 1); stB(Bz, cur ^ 1, vz); stB(Bh, cur ^ 1, vh);
        }
        __syncthreads();
    }

    // epilogue: GRU combine + elu -> g_h
#pragma unroll
    for (int mi = 0; mi < 2; mi++) {
#pragma unroll
        for (int ni = 0; ni < 8; ni++) {
            int c = nbase + wc + ni * 8 + t4 * 2;
            float bz0 = bxz[c] + bhz[c], bz1 = bxz[c + 1] + bhz[c + 1];
            float bh0 = bxh[c] + bhh[c], bh1 = bxh[c + 1] + bhh[c + 1];
#pragma unroll
            for (int hh = 0; hh < 2; hh++) {
                int r = mbase + wr + mi * 16 + grp + hh * 8;
                if (r < M_NODES) {
                    float z0 = 1.f / (1.f + expf(-(az[mi][ni][2 * hh + 0] + bz0)));
                    float z1 = 1.f / (1.f + expf(-(az[mi][ni][2 * hh + 1] + bz1)));
                    float t0 = tanhf(ah[mi][ni][2 * hh + 0] + bh0);
                    float t1 = tanhf(ah[mi][ni][2 * hh + 1] + bh1);
                    float h0 = (1.f - z0) * t0;
                    float h1 = (1.f - z1) * t1;
                    h0 = h0 > 0.f ? h0 : expm1f(h0);
                    h1 = h1 > 0.f ? h1 : expm1f(h1);
                    *reinterpret_cast<float2*>(&g_h[(size_t)r * CH + c]) =
                        make_float2(h0, h1);
                }
            }
        }
    }
}

// ---------------------------------------------------------------------------
// Kernel 2: out = g_h @ W_lin + b_lin
// ---------------------------------------------------------------------------
__global__ void __launch_bounds__(256, 1) readout_kernel(
    const float* __restrict__ Wl, const float* __restrict__ bl,
    float* __restrict__ out)
{
    const int tid  = threadIdx.x;
    const int warp = tid >> 5, lane = tid & 31;
    const int grp  = lane >> 2, t4 = lane & 3;
    const int wm   = warp & 3, wn = warp >> 2;
    const int wr   = wm * 32, wc = wn * 64;
    const int mbase = blockIdx.y * MT;
    const int nbase = blockIdx.x * NT;

    uint32_t* As = smem_u;           // [2][ASZ]
    uint32_t* Bl = smem_u + 2 * ASZ; // [2][BSZ]

    float acc[2][8][4];
#pragma unroll
    for (int i = 0; i < 2; i++)
#pragma unroll
        for (int j = 0; j < 8; j++)
#pragma unroll
            for (int k = 0; k < 4; k++) acc[i][j][k] = 0.f;

    float4 va[4], vb[4];

    auto ldA = [&](int kc) {
#pragma unroll
        for (int i = 0; i < 4; i++) {
            int f = tid + i * 256; int r = f >> 3, c4 = f & 7;
            int gr = mbase + r;
            va[i] = (gr < M_NODES)
                ? *reinterpret_cast<const float4*>(g_h + (size_t)gr * CH + kc + c4 * 4)
                : make_float4(0.f, 0.f, 0.f, 0.f);
        }
    };
    auto ldB = [&](int kc) {
#pragma unroll
        for (int i = 0; i < 4; i++) {
            int f = tid + i * 256; int k = f >> 5, n4 = f & 31;
            vb[i] = *reinterpret_cast<const float4*>(Wl + (size_t)(kc + k) * CH + nbase + n4 * 4);
        }
    };
    auto stA = [&](int buf) {
        uint32_t* d = As + buf * ASZ;
#pragma unroll
        for (int i = 0; i < 4; i++) {
            int f = tid + i * 256; int r = f >> 3, c4 = f & 7;
            uint4 u = make_uint4(f2tf(va[i].x), f2tf(va[i].y), f2tf(va[i].z), f2tf(va[i].w));
            *reinterpret_cast<uint4*>(d + r * APITCH + c4 * 4) = u;
        }
    };
    auto stB = [&](int buf) {
        uint32_t* d = Bl + buf * BSZ;
#pragma unroll
        for (int i = 0; i < 4; i++) {
            int f = tid + i * 256; int k = f >> 5, n4 = f & 31;
            uint4 u = make_uint4(f2tf(vb[i].x), f2tf(vb[i].y), f2tf(vb[i].z), f2tf(vb[i].w));
            *reinterpret_cast<uint4*>(d + k * BPITCH + n4 * 4) = u;
        }
    };

    auto compute = [&](int buf) {
        const uint32_t* A = As + buf * ASZ;
        const uint32_t* B = Bl + buf * BSZ;
#pragma unroll
        for (int ks = 0; ks < 4; ks++) {
            int k0 = ks * 8;
            uint32_t a[2][4];
#pragma unroll
            for (int mi = 0; mi < 2; mi++) {
                int r = wr + mi * 16 + grp;
                a[mi][0] = A[r * APITCH + k0 + t4];
                a[mi][1] = A[(r + 8) * APITCH + k0 + t4];
                a[mi][2] = A[r * APITCH + k0 + 4 + t4];
                a[mi][3] = A[(r + 8) * APITCH + k0 + 4 + t4];
            }
#pragma unroll
            for (int ni = 0; ni < 8; ni++) {
                int c = wc + ni * 8 + grp;
                uint32_t b0 = B[(k0 + t4) * BPITCH + c];
                uint32_t b1 = B[(k0 + 4 + t4) * BPITCH + c];
                mma8(acc[0][ni], a[0], b0, b1);
                mma8(acc[1][ni], a[1], b0, b1);
            }
        }
    };

    ldA(0); ldB(0);
    stA(0); stB(0);
    __syncthreads();
#pragma unroll 1
    for (int ch = 0; ch < NCHUNK; ch++) {
        int cur = ch & 1;
        if (ch + 1 < NCHUNK) { int kc = (ch + 1) * KT; ldA(kc); ldB(kc); }
        compute(cur);
        if (ch + 1 < NCHUNK) { stA(cur ^ 1); stB(cur ^ 1); }
        __syncthreads();
    }

#pragma unroll
    for (int mi = 0; mi < 2; mi++) {
#pragma unroll
        for (int ni = 0; ni < 8; ni++) {
            int c = nbase + wc + ni * 8 + t4 * 2;
            float b0 = bl[c], b1 = bl[c + 1];
#pragma unroll
            for (int hh = 0; hh < 2; hh++) {
                int r = mbase + wr + mi * 16 + grp + hh * 8;
                if (r < M_NODES) {
                    *reinterpret_cast<float2*>(&out[(size_t)r * CH + c]) =
                        make_float2(acc[mi][ni][2 * hh + 0] + b0,
                                    acc[mi][ni][2 * hh + 1] + b1);
                }
            }
        }
    }
}

// ---------------------------------------------------------------------------
extern "C" void kernel_launch(void* const* d_in, const int* in_sizes, int n_in,
                              void* d_out, int out_size)
{
    const float* x     = (const float*)d_in[0];
    const float* W_xz  = (const float*)d_in[3];
    const float* b_xz  = (const float*)d_in[4];
    const float* b_hz  = (const float*)d_in[6];
    const float* W_xh  = (const float*)d_in[11];
    const float* b_xh  = (const float*)d_in[12];
    const float* b_hh  = (const float*)d_in[14];
    const float* W_lin = (const float*)d_in[15];
    const float* b_lin = (const float*)d_in[16];
    float* out = (float*)d_out;

    const int SMEM1 = (2 * ASZ + 4 * BSZ) * 4;  // 106496 B
    const int SMEM2 = (2 * ASZ + 2 * BSZ) * 4;  //  71680 B

    static bool attr_done = false;
    if (!attr_done) {
        (void)cudaFuncSetAttribute(gates_kernel,
                                   cudaFuncAttributeMaxDynamicSharedMemorySize, SMEM1);
        (void)cudaFuncSetAttribute(readout_kernel,
                                   cudaFuncAttributeMaxDynamicSharedMemorySize, SMEM2);
        attr_done = true;
    }

    dim3 blk(256);
    dim3 grid(CH / NT, (M_NODES + MT - 1) / MT);  // (2, 782)

    gates_kernel<<<grid, blk, SMEM1>>>(x, W_xz, b_xz, b_hz, W_xh, b_xh, b_hh);
    readout_kernel<<<grid, blk, SMEM2>>>(W_lin, b_lin, out);
}

// round 5
// speedup vs baseline: 2.0757x; 2.0757x over previous
#include <cuda_runtime.h>
#include <cuda_fp16.h>
#include <stdint.h>

// ============================================================================
// GConvGRU (K=1 Cheb, H0=0) collapses to:
//   Z  = sigmoid(x@Wxz + bxz + bhz)
//   Ht = tanh   (x@Wxh + bxh + bhh)
//   h  = elu((1-Z)*Ht)
//   out = h@Wlin + blin
// Toolchain targets sm_100 (no 'a') -> tcgen05 unavailable. Fully fused
// fp16 mma.sync (m16n8k16) + ldmatrix.x4 kernel: per 128-row tile,
// x resident in smem (fp16), gates GEMM in two N-halves, GRU/elu epilogue
// -> h in smem (fp16), readout GEMM, biased fp32 store. Weights pre-
// transposed to N-major fp16 by a prep kernel.
// ============================================================================

#define M_NODES 100000
#define CH      256
#define MT      128
#define NTILES  782
#define THREADS 256

#define XSTRIDE 528               // 33 x 16B units -> ldmatrix conflict-free
#define WSTRIDE 80                // 5 x 16B units  -> ldmatrix conflict-free

#define OFF_BZ  0
#define OFF_BH  1024
#define OFF_BL  2048
#define OFF_X   3072
#define OFF_W   (OFF_X + 128 * XSTRIDE)        // 70656 ; 2 bufs x 20480
#define OFF_H   (OFF_W + 40960)                // 111616
#define SMEM_TOTAL (OFF_H + 128 * XSTRIDE)     // 179200 B

#define L2E 1.4426950408889634f

static __device__ __half g_wt[3 * CH * CH];    // n-major fp16: [w][n][k]

// ---------------------------------------------------------------------------
__device__ __forceinline__ uint32_t smem_u32(const void* p) {
    uint32_t a;
    asm("{ .reg .u64 t; cvta.to.shared.u64 t, %1; cvt.u32.u64 %0, t; }"
        : "=r"(a) : "l"(p));
    return a;
}
__device__ __forceinline__ float fex2(float x) {
    float y; asm("ex2.approx.f32 %0, %1;" : "=f"(y) : "f"(x)); return y;
}
__device__ __forceinline__ float frcp(float x) {
    float y; asm("rcp.approx.f32 %0, %1;" : "=f"(y) : "f"(x)); return y;
}
__device__ __forceinline__ void ldsm4(uint32_t r[4], uint32_t addr) {
    asm volatile("ldmatrix.sync.aligned.m8n8.x4.shared.b16 {%0,%1,%2,%3}, [%4];"
                 : "=r"(r[0]), "=r"(r[1]), "=r"(r[2]), "=r"(r[3]) : "r"(addr));
}
__device__ __forceinline__ void mma16(float c[4], const uint32_t a[4],
                                      uint32_t b0, uint32_t b1) {
    asm volatile(
        "mma.sync.aligned.m16n8k16.row.col.f32.f16.f16.f32 "
        "{%0,%1,%2,%3}, {%4,%5,%6,%7}, {%8,%9}, {%0,%1,%2,%3};"
        : "+f"(c[0]), "+f"(c[1]), "+f"(c[2]), "+f"(c[3])
        : "r"(a[0]), "r"(a[1]), "r"(a[2]), "r"(a[3]), "r"(b0), "r"(b1));
}
__device__ __forceinline__ uint32_t packh2(float a, float b) {
    __half2 h = __floats2half2_rn(a, b);
    return *reinterpret_cast<uint32_t*>(&h);
}

// ---------------------------------------------------------------------------
// Prep: Wt[n][k] = fp16(W[k][n]) for Wxz, Wxh, Wlin (n-major)
// ---------------------------------------------------------------------------
__global__ void prep_kernel(const float* __restrict__ Wz,
                            const float* __restrict__ Wh,
                            const float* __restrict__ Wl) {
    __shared__ float t[32][33];
    const float* W = (blockIdx.z == 0) ? Wz : (blockIdx.z == 1) ? Wh : Wl;
    __half* Wt = g_wt + (size_t)blockIdx.z * CH * CH;
    int n0 = blockIdx.x * 32, k0 = blockIdx.y * 32;
    int tx = threadIdx.x, ty = threadIdx.y;   // 32 x 8
#pragma unroll
    for (int r = 0; r < 4; r++)
        t[ty + r * 8][tx] = W[(size_t)(k0 + ty + r * 8) * CH + n0 + tx];
    __syncthreads();
#pragma unroll
    for (int r = 0; r < 4; r++)
        Wt[(size_t)(n0 + ty + r * 8) * CH + k0 + tx] =
            __float2half_rn(t[tx][ty + r * 8]);
}

// ---------------------------------------------------------------------------
// Fused main kernel: one CTA per 128-row tile, 8 warps (4m x 2n)
// ---------------------------------------------------------------------------
__global__ void __launch_bounds__(THREADS, 1) fused_kernel(
    const float* __restrict__ x,
    const float* __restrict__ bxz, const float* __restrict__ bhz,
    const float* __restrict__ bxh, const float* __restrict__ bhh,
    const float* __restrict__ blin,
    float* __restrict__ out)
{
    extern __shared__ char smem[];
    const uint32_t sbase = smem_u32(smem);
    const int tid = threadIdx.x, wid = tid >> 5, lane = tid & 31;
    const int grp = lane >> 2, t4 = lane & 3;
    const int wm = wid & 3, wn = wid >> 2;
    const int wr = wm * 32;
    const int mbase = blockIdx.x * MT;

    float* bzs = (float*)(smem + OFF_BZ);
    float* bhs = (float*)(smem + OFF_BH);
    float* bls = (float*)(smem + OFF_BL);
    bzs[tid] = bxz[tid] + bhz[tid];
    bhs[tid] = bxh[tid] + bhh[tid];
    bls[tid] = blin[tid];

    // ---- stage X tile (fp32 -> fp16, resident) ----
#pragma unroll
    for (int i = 0; i < 16; i++) {
        int idx = i * THREADS + tid;          // 0..4095
        int r = idx >> 5, c16 = idx & 31;     // 32 x 16B chunks per row
        int gr = mbase + r;
        float4 v0 = make_float4(0.f, 0.f, 0.f, 0.f), v1 = v0;
        if (gr < M_NODES) {
            const float* p = x + (size_t)gr * CH + c16 * 8;
            v0 = *(const float4*)(p);
            v1 = *(const float4*)(p + 4);
        }
        uint4 u = make_uint4(packh2(v0.x, v0.y), packh2(v0.z, v0.w),
                             packh2(v1.x, v1.y), packh2(v1.z, v1.w));
        *(uint4*)(smem + OFF_X + r * XSTRIDE + c16 * 16) = u;
    }
    __syncthreads();

    const __half* wtz = g_wt;
    const __half* wth = g_wt + CH * CH;
    const __half* wtl = g_wt + 2 * CH * CH;

    // per-lane ldmatrix base addresses (lane&15 = row, lane>>4 = k-halfstep)
    const uint32_t xa = sbase + OFF_X + (uint32_t)(wr + (lane & 15)) * XSTRIDE
                        + ((lane >> 4) << 4);
    const uint32_t ha = sbase + OFF_H + (uint32_t)(wr + (lane & 15)) * XSTRIDE
                        + ((lane >> 4) << 4);
    const uint32_t bb = sbase + OFF_W + (uint32_t)(lane & 15) * WSTRIDE
                        + ((lane >> 4) << 4);

    // ======================= gates: two N-halves =======================
#pragma unroll 1
    for (int nh = 0; nh < 2; nh++) {
        float az[2][8][4], ah[2][8][4];
#pragma unroll
        for (int i = 0; i < 2; i++)
#pragma unroll
            for (int j = 0; j < 8; j++)
#pragma unroll
                for (int k = 0; k < 4; k++) { az[i][j][k] = 0.f; ah[i][j][k] = 0.f; }

        uint4 vz[2], vh[2];
        auto ldgW = [&](int ch) {
#pragma unroll
            for (int i = 0; i < 2; i++) {
                int idx = i * THREADS + tid;
                int n = idx >> 2, u = idx & 3;
                size_t o = (size_t)(nh * 128 + n) * CH + ch * 32 + u * 8;
                vz[i] = *(const uint4*)(wtz + o);
                vh[i] = *(const uint4*)(wth + o);
            }
        };
        auto stsW = [&](int bi) {
#pragma unroll
            for (int i = 0; i < 2; i++) {
                int idx = i * THREADS + tid;
                int n = idx >> 2, u = idx & 3;
                *(uint4*)(smem + OFF_W + bi * 20480 + n * WSTRIDE + u * 16) = vz[i];
                *(uint4*)(smem + OFF_W + bi * 20480 + 10240 + n * WSTRIDE + u * 16) = vh[i];
            }
        };

        ldgW(0); stsW(0);
        __syncthreads();
#pragma unroll 1
        for (int ch = 0; ch < 8; ch++) {
            const int bi = ch & 1;
            if (ch < 7) ldgW(ch + 1);
#pragma unroll
            for (int ks = 0; ks < 2; ks++) {
                uint32_t a[2][4];
#pragma unroll
                for (int mi = 0; mi < 2; mi++)
                    ldsm4(a[mi], xa + mi * 16 * XSTRIDE + ch * 64 + ks * 32);
#pragma unroll
                for (int p = 0; p < 4; p++) {
                    uint32_t bz4[4], bh4[4];
                    uint32_t bo = bb + bi * 20480
                                  + (uint32_t)(wn * 64 + p * 16) * WSTRIDE + ks * 32;
                    ldsm4(bz4, bo);
                    ldsm4(bh4, bo + 10240);
                    mma16(az[0][2 * p],     a[0], bz4[0], bz4[2]);
                    mma16(az[1][2 * p],     a[1], bz4[0], bz4[2]);
                    mma16(az[0][2 * p + 1], a[0], bz4[1], bz4[3]);
                    mma16(az[1][2 * p + 1], a[1], bz4[1], bz4[3]);
                    mma16(ah[0][2 * p],     a[0], bh4[0], bh4[2]);
                    mma16(ah[1][2 * p],     a[1], bh4[0], bh4[2]);
                    mma16(ah[0][2 * p + 1], a[0], bh4[1], bh4[3]);
                    mma16(ah[1][2 * p + 1], a[1], bh4[1], bh4[3]);
                }
            }
            if (ch < 7) stsW((ch + 1) & 1);
            __syncthreads();
        }

        // ---- GRU/elu epilogue -> H (fp16 smem) ----
#pragma unroll
        for (int mi = 0; mi < 2; mi++) {
#pragma unroll
            for (int ni = 0; ni < 8; ni++) {
                int col = nh * 128 + wn * 64 + ni * 8 + 2 * t4;
                float bz0 = bzs[col], bz1 = bzs[col + 1];
                float bh0 = bhs[col], bh1 = bhs[col + 1];
#pragma unroll
                for (int hh = 0; hh < 2; hh++) {
                    int row = wr + mi * 16 + grp + hh * 8;
                    float a0 = az[mi][ni][2 * hh + 0] + bz0;
                    float a1 = az[mi][ni][2 * hh + 1] + bz1;
                    float c0 = ah[mi][ni][2 * hh + 0] + bh0;
                    float c1 = ah[mi][ni][2 * hh + 1] + bh1;
                    float zp0 = frcp(1.f + fex2(a0 * L2E));      // 1 - sigmoid
                    float zp1 = frcp(1.f + fex2(a1 * L2E));
                    float t0 = 1.f - 2.f * frcp(fex2(c0 * (2.f * L2E)) + 1.f);
                    float t1 = 1.f - 2.f * frcp(fex2(c1 * (2.f * L2E)) + 1.f);
                    float v0 = zp0 * t0, v1 = zp1 * t1;
                    v0 = (v0 > 0.f) ? v0 : (fex2(v0 * L2E) - 1.f);
                    v1 = (v1 > 0.f) ? v1 : (fex2(v1 * L2E) - 1.f);
                    *(uint32_t*)(smem + OFF_H + row * XSTRIDE + col * 2) =
                        packh2(v0, v1);
                }
            }
        }
        __syncthreads();
    }

    // ======================= readout: out = H @ WlT + bl ===============
    {
        float o[2][16][4];
#pragma unroll
        for (int i = 0; i < 2; i++)
#pragma unroll
            for (int j = 0; j < 16; j++)
#pragma unroll
                for (int k = 0; k < 4; k++) o[i][j][k] = 0.f;

        uint4 vl[4];
        auto ldgL = [&](int ch) {
#pragma unroll
            for (int i = 0; i < 4; i++) {
                int idx = i * THREADS + tid;
                int n = idx >> 2, u = idx & 3;
                vl[i] = *(const uint4*)(wtl + (size_t)n * CH + ch * 32 + u * 8);
            }
        };
        auto stsL = [&](int bi) {
#pragma unroll
            for (int i = 0; i < 4; i++) {
                int idx = i * THREADS + tid;
                int n = idx >> 2, u = idx & 3;
                *(uint4*)(smem + OFF_W + bi * 20480 + n * WSTRIDE + u * 16) = vl[i];
            }
        };

        ldgL(0); stsL(0);
        __syncthreads();
#pragma unroll 1
        for (int ch = 0; ch < 8; ch++) {
            const int bi = ch & 1;
            if (ch < 7) ldgL(ch + 1);
#pragma unroll
            for (int ks = 0; ks < 2; ks++) {
                uint32_t a[2][4];
#pragma unroll
                for (int mi = 0; mi < 2; mi++)
                    ldsm4(a[mi], ha + mi * 16 * XSTRIDE + ch * 64 + ks * 32);
#pragma unroll
                for (int p = 0; p < 8; p++) {
                    uint32_t b4[4];
                    ldsm4(b4, bb + bi * 20480
                              + (uint32_t)(wn * 128 + p * 16) * WSTRIDE + ks * 32);
                    mma16(o[0][2 * p],     a[0], b4[0], b4[2]);
                    mma16(o[1][2 * p],     a[1], b4[0], b4[2]);
                    mma16(o[0][2 * p + 1], a[0], b4[1], b4[3]);
                    mma16(o[1][2 * p + 1], a[1], b4[1], b4[3]);
                }
            }
            if (ch < 7) stsL((ch + 1) & 1);
            __syncthreads();
        }

        // ---- biased store ----
#pragma unroll
        for (int mi = 0; mi < 2; mi++) {
#pragma unroll
            for (int ni = 0; ni < 16; ni++) {
                int col = wn * 128 + ni * 8 + 2 * t4;
                float b0 = bls[col], b1 = bls[col + 1];
#pragma unroll
                for (int hh = 0; hh < 2; hh++) {
                    int gr = mbase + wr + mi * 16 + grp + hh * 8;
                    if (gr < M_NODES) {
                        *(float2*)(out + (size_t)gr * CH + col) =
                            make_float2(o[mi][ni][2 * hh + 0] + b0,
                                        o[mi][ni][2 * hh + 1] + b1);
                    }
                }
            }
        }
    }
}

// ---------------------------------------------------------------------------
extern "C" void kernel_launch(void* const* d_in, const int* in_sizes, int n_in,
                              void* d_out, int out_size)
{
    const float* x     = (const float*)d_in[0];
    const float* W_xz  = (const float*)d_in[3];
    const float* b_xz  = (const float*)d_in[4];
    const float* b_hz  = (const float*)d_in[6];
    const float* W_xh  = (const float*)d_in[11];
    const float* b_xh  = (const float*)d_in[12];
    const float* b_hh  = (const float*)d_in[14];
    const float* W_lin = (const float*)d_in[15];
    const float* b_lin = (const float*)d_in[16];
    float* out = (float*)d_out;

    static bool attr_done = false;
    if (!attr_done) {
        (void)cudaFuncSetAttribute(fused_kernel,
                                   cudaFuncAttributeMaxDynamicSharedMemorySize,
                                   SMEM_TOTAL);
        attr_done = true;
    }

    prep_kernel<<<dim3(8, 8, 3), dim3(32, 8)>>>(W_xz, W_xh, W_lin);
    fused_kernel<<<NTILES, THREADS, SMEM_TOTAL>>>(x, b_xz, b_hz, b_xh, b_hh,
                                                  b_lin, out);
}

// round 7
// speedup vs baseline: 2.1606x; 1.0409x over previous
#include <cuda_runtime.h>
#include <cuda_fp16.h>
#include <stdint.h>

// ============================================================================
// GConvGRU (K=1 Cheb, H0=0) collapses to:
//   Z  = sigmoid(x@Wxz + bxz + bhz)
//   Ht = tanh   (x@Wxh + bxh + bhh)
//   h  = elu((1-Z)*Ht)
//   out = h@Wlin + blin
// sm_100 toolchain (no tcgen05). Fused fp16 mma.sync (m16n8k16) + ldmatrix
// kernel, 512 threads / 16 warps (4m x 4n) per 128-row tile for issue-level
// parallelism. x resident in smem fp16; gates GEMM in two N-halves; GRU/elu
// epilogue -> h in smem fp16; readout GEMM; biased fp32 store. Weights
// pre-transposed to N-major fp16 by a prep kernel.
// ============================================================================

#define M_NODES 100000
#define CH      256
#define MT      128
#define NTILES  782
#define THREADS 512

#define XSTRIDE 528               // 33 x 16B units -> ldmatrix conflict-free
#define WSTRIDE 80                // 5 x 16B units  -> ldmatrix conflict-free

#define OFF_BZ  0
#define OFF_BH  1024
#define OFF_BL  2048
#define OFF_X   3072
#define OFF_W   (OFF_X + 128 * XSTRIDE)        // 70656 ; 2 bufs x 20480
#define OFF_H   (OFF_W + 40960)                // 111616
#define SMEM_TOTAL (OFF_H + 128 * XSTRIDE)     // 179200 B

#define L2E 1.4426950408889634f

static __device__ __half g_wt[3 * CH * CH];    // n-major fp16: [w][n][k]

// ---------------------------------------------------------------------------
__device__ __forceinline__ uint32_t smem_u32(const void* p) {
    uint32_t a;
    asm("{ .reg .u64 t; cvta.to.shared.u64 t, %1; cvt.u32.u64 %0, t; }"
        : "=r"(a) : "l"(p));
    return a;
}
__device__ __forceinline__ float fex2(float x) {
    float y; asm("ex2.approx.f32 %0, %1;" : "=f"(y) : "f"(x)); return y;
}
__device__ __forceinline__ float frcp(float x) {
    float y; asm("rcp.approx.f32 %0, %1;" : "=f"(y) : "f"(x)); return y;
}
__device__ __forceinline__ void ldsm4(uint32_t r[4], uint32_t addr) {
    asm volatile("ldmatrix.sync.aligned.m8n8.x4.shared.b16 {%0,%1,%2,%3}, [%4];"
                 : "=r"(r[0]), "=r"(r[1]), "=r"(r[2]), "=r"(r[3]) : "r"(addr));
}
__device__ __forceinline__ void mma16(float c[4], const uint32_t a[4],
                                      uint32_t b0, uint32_t b1) {
    asm volatile(
        "mma.sync.aligned.m16n8k16.row.col.f32.f16.f16.f32 "
        "{%0,%1,%2,%3}, {%4,%5,%6,%7}, {%8,%9}, {%0,%1,%2,%3};"
        : "+f"(c[0]), "+f"(c[1]), "+f"(c[2]), "+f"(c[3])
        : "r"(a[0]), "r"(a[1]), "r"(a[2]), "r"(a[3]), "r"(b0), "r"(b1));
}
__device__ __forceinline__ uint32_t packh2(float a, float b) {
    __half2 h = __floats2half2_rn(a, b);
    return *reinterpret_cast<uint32_t*>(&h);
}

// ---------------------------------------------------------------------------
// Prep: Wt[n][k] = fp16(W[k][n]) for Wxz, Wxh, Wlin (n-major)
// ---------------------------------------------------------------------------
__global__ void prep_kernel(const float* __restrict__ Wz,
                            const float* __restrict__ Wh,
                            const float* __restrict__ Wl) {
    __shared__ float t[32][33];
    const float* W = (blockIdx.z == 0) ? Wz : (blockIdx.z == 1) ? Wh : Wl;
    __half* Wt = g_wt + (size_t)blockIdx.z * CH * CH;
    int n0 = blockIdx.x * 32, k0 = blockIdx.y * 32;
    int tx = threadIdx.x, ty = threadIdx.y;   // 32 x 8
#pragma unroll
    for (int r = 0; r < 4; r++)
        t[ty + r * 8][tx] = W[(size_t)(k0 + ty + r * 8) * CH + n0 + tx];
    __syncthreads();
#pragma unroll
    for (int r = 0; r < 4; r++)
        Wt[(size_t)(n0 + ty + r * 8) * CH + k0 + tx] =
            __float2half_rn(t[tx][ty + r * 8]);
}

// ---------------------------------------------------------------------------
// Fused main kernel: one CTA per 128-row tile, 16 warps (4m x 4n)
// ---------------------------------------------------------------------------
__global__ void __launch_bounds__(THREADS, 1) fused_kernel(
    const float* __restrict__ x,
    const float* __restrict__ bxz, const float* __restrict__ bhz,
    const float* __restrict__ bxh, const float* __restrict__ bhh,
    const float* __restrict__ blin,
    float* __restrict__ out)
{
    extern __shared__ char smem[];
    const uint32_t sbase = smem_u32(smem);
    const int tid = threadIdx.x, wid = tid >> 5, lane = tid & 31;
    const int grp = lane >> 2, t4 = lane & 3;
    const int wm = wid & 3, wn = wid >> 2;      // 4m x 4n
    const int wr = wm * 32;
    const int mbase = blockIdx.x * MT;

    float* bzs = (float*)(smem + OFF_BZ);
    float* bhs = (float*)(smem + OFF_BH);
    float* bls = (float*)(smem + OFF_BL);
    if (tid < CH) {
        bzs[tid] = bxz[tid] + bhz[tid];
        bhs[tid] = bxh[tid] + bhh[tid];
        bls[tid] = blin[tid];
    }

    // ---- stage X tile (fp32 -> fp16, resident) ----
#pragma unroll
    for (int i = 0; i < 8; i++) {
        int idx = i * THREADS + tid;          // 0..4095
        int r = idx >> 5, c16 = idx & 31;     // 32 x 16B chunks per row
        int gr = mbase + r;
        float4 v0 = make_float4(0.f, 0.f, 0.f, 0.f), v1 = v0;
        if (gr < M_NODES) {
            const float* p = x + (size_t)gr * CH + c16 * 8;
            v0 = *(const float4*)(p);
            v1 = *(const float4*)(p + 4);
        }
        uint4 u = make_uint4(packh2(v0.x, v0.y), packh2(v0.z, v0.w),
                             packh2(v1.x, v1.y), packh2(v1.z, v1.w));
        *(uint4*)(smem + OFF_X + r * XSTRIDE + c16 * 16) = u;
    }
    __syncthreads();

    const __half* wtz = g_wt;
    const __half* wth = g_wt + CH * CH;
    const __half* wtl = g_wt + 2 * CH * CH;

    // per-lane ldmatrix base addresses (lane&15 = row, lane>>4 = k-halfstep)
    const uint32_t xa = sbase + OFF_X + (uint32_t)(wr + (lane & 15)) * XSTRIDE
                        + ((lane >> 4) << 4);
    const uint32_t ha = sbase + OFF_H + (uint32_t)(wr + (lane & 15)) * XSTRIDE
                        + ((lane >> 4) << 4);
    const uint32_t bb = sbase + OFF_W + (uint32_t)(lane & 15) * WSTRIDE
                        + ((lane >> 4) << 4);

    // staging index: 512 threads cover 128 n-rows x 4 16B-chunks
    const int sn = tid >> 2, su = tid & 3;

    // ======================= gates: two N-halves =======================
#pragma unroll 1
    for (int nh = 0; nh < 2; nh++) {
        float az[2][4][4], ah[2][4][4];
#pragma unroll
        for (int i = 0; i < 2; i++)
#pragma unroll
            for (int j = 0; j < 4; j++)
#pragma unroll
                for (int k = 0; k < 4; k++) { az[i][j][k] = 0.f; ah[i][j][k] = 0.f; }

        uint4 vz, vh;
        auto ldgW = [&](int ch) {
            size_t o = (size_t)(nh * 128 + sn) * CH + ch * 32 + su * 8;
            vz = *(const uint4*)(wtz + o);
            vh = *(const uint4*)(wth + o);
        };
        auto stsW = [&](int bi) {
            *(uint4*)(smem + OFF_W + bi * 20480 + sn * WSTRIDE + su * 16) = vz;
            *(uint4*)(smem + OFF_W + bi * 20480 + 10240 + sn * WSTRIDE + su * 16) = vh;
        };

        ldgW(0); stsW(0);
        __syncthreads();
#pragma unroll 1
        for (int ch = 0; ch < 8; ch++) {
            const int bi = ch & 1;
            if (ch < 7) ldgW(ch + 1);
#pragma unroll
            for (int ks = 0; ks < 2; ks++) {
                uint32_t a[2][4];
#pragma unroll
                for (int mi = 0; mi < 2; mi++)
                    ldsm4(a[mi], xa + mi * 16 * XSTRIDE + ch * 64 + ks * 32);
#pragma unroll
                for (int p = 0; p < 2; p++) {
                    uint32_t bz4[4], bh4[4];
                    uint32_t bo = bb + bi * 20480
                                  + (uint32_t)(wn * 32 + p * 16) * WSTRIDE + ks * 32;
                    ldsm4(bz4, bo);
                    ldsm4(bh4, bo + 10240);
                    mma16(az[0][2 * p],     a[0], bz4[0], bz4[2]);
                    mma16(az[1][2 * p],     a[1], bz4[0], bz4[2]);
                    mma16(az[0][2 * p + 1], a[0], bz4[1], bz4[3]);
                    mma16(az[1][2 * p + 1], a[1], bz4[1], bz4[3]);
                    mma16(ah[0][2 * p],     a[0], bh4[0], bh4[2]);
                    mma16(ah[1][2 * p],     a[1], bh4[0], bh4[2]);
                    mma16(ah[0][2 * p + 1], a[0], bh4[1], bh4[3]);
                    mma16(ah[1][2 * p + 1], a[1], bh4[1], bh4[3]);
                }
            }
            if (ch < 7) stsW((ch + 1) & 1);
            __syncthreads();
        }

        // ---- GRU/elu epilogue -> H (fp16 smem) ----
#pragma unroll
        for (int mi = 0; mi < 2; mi++) {
#pragma unroll
            for (int ni = 0; ni < 4; ni++) {
                int col = nh * 128 + wn * 32 + ni * 8 + 2 * t4;
                float bz0 = bzs[col], bz1 = bzs[col + 1];
                float bh0 = bhs[col], bh1 = bhs[col + 1];
#pragma unroll
                for (int hh = 0; hh < 2; hh++) {
                    int row = wr + mi * 16 + grp + hh * 8;
                    float a0 = az[mi][ni][2 * hh + 0] + bz0;
                    float a1 = az[mi][ni][2 * hh + 1] + bz1;
                    float c0 = ah[mi][ni][2 * hh + 0] + bh0;
                    float c1 = ah[mi][ni][2 * hh + 1] + bh1;
                    float zp0 = frcp(1.f + fex2(a0 * L2E));      // 1 - sigmoid
                    float zp1 = frcp(1.f + fex2(a1 * L2E));
                    float t0 = 1.f - 2.f * frcp(fex2(c0 * (2.f * L2E)) + 1.f);
                    float t1 = 1.f - 2.f * frcp(fex2(c1 * (2.f * L2E)) + 1.f);
                    float v0 = zp0 * t0, v1 = zp1 * t1;
                    v0 = (v0 > 0.f) ? v0 : (fex2(v0 * L2E) - 1.f);
                    v1 = (v1 > 0.f) ? v1 : (fex2(v1 * L2E) - 1.f);
                    *(uint32_t*)(smem + OFF_H + row * XSTRIDE + col * 2) =
                        packh2(v0, v1);
                }
            }
        }
        __syncthreads();
    }

    // ======================= readout: out = H @ WlT + bl ===============
    {
        float o[2][8][4];
#pragma unroll
        for (int i = 0; i < 2; i++)
#pragma unroll
            for (int j = 0; j < 8; j++)
#pragma unroll
                for (int k = 0; k < 4; k++) o[i][j][k] = 0.f;

        uint4 vl[2];
        auto ldgL = [&](int ch) {
#pragma unroll
            for (int i = 0; i < 2; i++) {
                int idx = i * THREADS + tid;
                int n = idx >> 2, u = idx & 3;
                vl[i] = *(const uint4*)(wtl + (size_t)n * CH + ch * 32 + u * 8);
            }
        };
        auto stsL = [&](int bi) {
#pragma unroll
            for (int i = 0; i < 2; i++) {
                int idx = i * THREADS + tid;
                int n = idx >> 2, u = idx & 3;
                *(uint4*)(smem + OFF_W + bi * 20480 + n * WSTRIDE + u * 16) = vl[i];
            }
        };

        ldgL(0); stsL(0);
        __syncthreads();
#pragma unroll 1
        for (int ch = 0; ch < 8; ch++) {
            const int bi = ch & 1;
            if (ch < 7) ldgL(ch + 1);
#pragma unroll
            for (int ks = 0; ks < 2; ks++) {
                uint32_t a[2][4];
#pragma unroll
                for (int mi = 0; mi < 2; mi++)
                    ldsm4(a[mi], ha + mi * 16 * XSTRIDE + ch * 64 + ks * 32);
#pragma unroll
                for (int p = 0; p < 4; p++) {
                    uint32_t b4[4];
                    ldsm4(b4, bb + bi * 20480
                              + (uint32_t)(wn * 64 + p * 16) * WSTRIDE + ks * 32);
                    mma16(o[0][2 * p],     a[0], b4[0], b4[2]);
                    mma16(o[1][2 * p],     a[1], b4[0], b4[2]);
                    mma16(o[0][2 * p + 1], a[0], b4[1], b4[3]);
                    mma16(o[1][2 * p + 1], a[1], b4[1], b4[3]);
                }
            }
            if (ch < 7) stsL((ch + 1) & 1);
            __syncthreads();
        }

        // ---- biased store ----
#pragma unroll
        for (int mi = 0; mi < 2; mi++) {
#pragma unroll
            for (int ni = 0; ni < 8; ni++) {
                int col = wn * 64 + ni * 8 + 2 * t4;
                float b0 = bls[col], b1 = bls[col + 1];
#pragma unroll
                for (int hh = 0; hh < 2; hh++) {
                    int gr = mbase + wr + mi * 16 + grp + hh * 8;
                    if (gr < M_NODES) {
                        *(float2*)(out + (size_t)gr * CH + col) =
                            make_float2(o[mi][ni][2 * hh + 0] + b0,
                                        o[mi][ni][2 * hh + 1] + b1);
                    }
                }
            }
        }
    }
}

// ---------------------------------------------------------------------------
extern "C" void kernel_launch(void* const* d_in, const int* in_sizes, int n_in,
                              void* d_out, int out_size)
{
    const float* x     = (const float*)d_in[0];
    const float* W_xz  = (const float*)d_in[3];
    const float* b_xz  = (const float*)d_in[4];
    const float* b_hz  = (const float*)d_in[6];
    const float* W_xh  = (const float*)d_in[11];
    const float* b_xh  = (const float*)d_in[12];
    const float* b_hh  = (const float*)d_in[14];
    const float* W_lin = (const float*)d_in[15];
    const float* b_lin = (const float*)d_in[16];
    float* out = (float*)d_out;

    static bool attr_done = false;
    if (!attr_done) {
        (void)cudaFuncSetAttribute(fused_kernel,
                                   cudaFuncAttributeMaxDynamicSharedMemorySize,
                                   SMEM_TOTAL);
        attr_done = true;
    }

    prep_kernel<<<dim3(8, 8, 3), dim3(32, 8)>>>(W_xz, W_xh, W_lin);
    fused_kernel<<<NTILES, THREADS, SMEM_TOTAL>>>(x, b_xz, b_hz, b_xh, b_hh,
                                                  b_lin, out);
}